// round 5
// baseline (speedup 1.0000x reference)
#include <cuda_runtime.h>
#include <cstdint>

#define NUM_ITEMS 6714
#define N2 3357            // float2 per row
#define RANK 100
#define NTHREADS 256
#define KPT 14             // float2 per thread
#define THRESH_F 2.0f      // fast-path filter; count(>=2.0) ~ 153 per row for this data
#define CAND_CAP 1024
#define STOP2 144
#define FINAL_CAP 256
#define MAXWRED 80

__device__ __forceinline__ uint32_t flip_f32(uint32_t s) {
    return s ^ ((s & 0x80000000u) ? 0xFFFFFFFFu : 0x80000000u);
}
__device__ __forceinline__ float unflip_f32(uint32_t k) {
    uint32_t s = (k & 0x80000000u) ? (k ^ 0x80000000u) : ~k;
    return __uint_as_float(s);
}

struct Shared {
    unsigned long long cand[CAND_CAP];  // ((u64)(~key)<<32)|idx : ascending == (key desc, idx asc)
    unsigned long long fin[FINAL_CAP];
    uint32_t wred[MAXWRED][8];
    uint32_t cnt0, cntF;
    int found;
    float labelval;
};

__global__ __launch_bounds__(NTHREADS) void logit_selector_kernel(
    const float* __restrict__ output,
    const int* __restrict__ labels,
    float* __restrict__ out_vals,
    float* __restrict__ out_labels)
{
    __shared__ Shared s;

    const int row  = blockIdx.x;
    const int tid  = threadIdx.x;
    const int lane = tid & 31;
    const int wid  = tid >> 5;
    const float* row_ptr = output + (size_t)row * NUM_ITEMS;
    const float2* row2 = reinterpret_cast<const float2*>(row_ptr);
    const int label = labels[row];

    if (tid == 0) {
        s.cnt0 = 0u; s.cntF = 0u; s.found = -1;
        s.labelval = row_ptr[label];
    }
    __syncthreads();

    // ---- fast path: stream + fixed-threshold filter + warp-aggregated compact ----
    // All 14 iterations executed by every thread (full-warp collectives safe).
    #pragma unroll
    for (int j = 0; j < KPT; ++j) {
        int i2 = tid + j * NTHREADS;
        bool valid = (i2 < N2);
        float2 v;
        if (valid) v = row2[i2]; else { v.x = -1e30f; v.y = -1e30f; }
        bool pa = v.x >= THRESH_F;
        bool pb = v.y >= THRESH_F;
        uint32_t ma = __ballot_sync(0xFFFFFFFFu, pa);
        uint32_t mb = __ballot_sync(0xFFFFFFFFu, pb);
        if (ma | mb) {
            uint32_t tot = (uint32_t)(__popc(ma) + __popc(mb));
            uint32_t base = 0;
            if (lane == 0) base = atomicAdd(&s.cnt0, tot);
            base = __shfl_sync(0xFFFFFFFFu, base, 0);
            uint32_t lmask = (1u << lane) - 1u;
            if (pa) {
                uint32_t key = flip_f32(__float_as_uint(v.x));
                uint32_t pos = base + (uint32_t)__popc(ma & lmask);
                if (pos < CAND_CAP)
                    s.cand[pos] = ((unsigned long long)(~key) << 32) | (uint32_t)(2 * i2);
            }
            if (pb) {
                uint32_t key = flip_f32(__float_as_uint(v.y));
                uint32_t pos = base + (uint32_t)__popc(ma) + (uint32_t)__popc(mb & lmask);
                if (pos < CAND_CAP)
                    s.cand[pos] = ((unsigned long long)(~key) << 32) | (uint32_t)(2 * i2 + 1);
            }
        }
    }
    __syncthreads();

    int iter = 0;

    // ---- fallback: exact bit-narrowing from global (never runs on this data) ----
    const uint32_t raw0 = s.cnt0;
    if (raw0 < RANK || raw0 > CAND_CAP) {
        __syncthreads();
        if (tid == 0) s.cnt0 = 0u;
        __syncthreads();
        uint32_t pfx = 0u, k = RANK, cand = NUM_ITEMS;
        int sh = 31;
        while (cand > (CAND_CAP - RANK) && sh >= 0 && iter < MAXWRED) {
            const uint32_t t = (pfx << 1) | 1u;
            int c = 0;
            for (int i = tid; i < NUM_ITEMS; i += NTHREADS)
                c += ((flip_f32(__float_as_uint(row_ptr[i])) >> sh) == t);
            c = __reduce_add_sync(0xFFFFFFFFu, c);
            if (lane == 0) s.wred[iter][wid] = (uint32_t)c;
            __syncthreads();
            uint32_t cnt1 = 0;
            #pragma unroll
            for (int w = 0; w < 8; ++w) cnt1 += s.wred[iter][w];
            if (cnt1 >= k) { pfx = t; cand = cnt1; }
            else           { k -= cnt1; pfx <<= 1; cand -= cnt1; }
            --sh; ++iter;
        }
        const uint32_t tf = (sh >= 31) ? 0u : (pfx << (sh + 1));
        for (int i = tid; i < NUM_ITEMS; i += NTHREADS) {
            uint32_t key = flip_f32(__float_as_uint(row_ptr[i]));
            if (key >= tf) {
                uint32_t pos = atomicAdd(&s.cnt0, 1u);   // plain atomics: no collectives
                if (pos < CAND_CAP)
                    s.cand[pos] = ((unsigned long long)(~key) << 32) | (uint32_t)i;
            }
        }
        __syncthreads();
    }
    const uint32_t cnt0 = min(s.cnt0, (uint32_t)CAND_CAP);
    const uint32_t cnt0_pad = (cnt0 + NTHREADS - 1) / NTHREADS * NTHREADS;

    // ---- bit-narrowing over the candidate set down to <= STOP2 ----
    const uint32_t* ch = reinterpret_cast<const uint32_t*>(s.cand);  // hi word at 2*i+1
    uint32_t pfx = 0u, k = RANK, cand = cnt0;
    int sh = 31;
    while (cand > STOP2 && sh >= 0 && iter < MAXWRED) {
        const uint32_t t = (pfx << 1) | 1u;
        int c = 0;
        for (uint32_t i = tid; i < cnt0; i += NTHREADS) {
            uint32_t key = ~ch[2 * i + 1];
            c += ((key >> sh) == t);
        }
        c = __reduce_add_sync(0xFFFFFFFFu, c);   // warp reconverged after loop exit
        if (lane == 0) s.wred[iter][wid] = (uint32_t)c;
        __syncthreads();
        uint32_t cnt1 = 0;
        #pragma unroll
        for (int w = 0; w < 8; ++w) cnt1 += s.wred[iter][w];
        if (cnt1 >= k) { pfx = t; cand = cnt1; }
        else           { k -= cnt1; pfx <<= 1; cand -= cnt1; }
        --sh; ++iter;
    }
    const uint32_t thresh2 = (sh >= 31) ? 0u : (pfx << (sh + 1));

    // ---- gather qualifiers (<= RANK-1 + STOP2 <= FINAL_CAP) via padded ballot loop ----
    for (uint32_t i = tid; i < cnt0_pad; i += NTHREADS) {
        unsigned long long p64 = 0ull;
        bool p = false;
        if (i < cnt0) {
            p64 = s.cand[i];
            p = (~(uint32_t)(p64 >> 32)) >= thresh2;
        }
        uint32_t m = __ballot_sync(0xFFFFFFFFu, p);
        if (m) {
            uint32_t base = 0;
            if (lane == 0) base = atomicAdd(&s.cntF, (uint32_t)__popc(m));
            base = __shfl_sync(0xFFFFFFFFu, base, 0);
            if (p) {
                uint32_t pos = base + (uint32_t)__popc(m & ((1u << lane) - 1u));
                if (pos < FINAL_CAP) s.fin[pos] = p64;
            }
        }
    }
    __syncthreads();
    const uint32_t cntF = min(s.cntF, (uint32_t)FINAL_CAP);

    // ---- exact rank via O(n^2) over <= ~240 candidates (broadcast LDS) ----
    int myj = -1;
    float myv = 0.0f;
    if (tid < (int)cntF) {
        unsigned long long p64 = s.fin[tid];
        int r = 0;
        for (uint32_t i = 0; i < cntF; ++i)
            r += (s.fin[i] < p64);
        if (r < RANK) {
            myj = (RANK - 1) - r;
            myv = unflip_f32(~(uint32_t)(p64 >> 32));
            if ((uint32_t)(p64 & 0xFFFFFFFFu) == (uint32_t)label)
                s.found = myj;
        }
    }
    __syncthreads();
    const int found = s.found;

    float* out_row = out_vals + (size_t)row * RANK;
    if (myj >= 0) {
        float v = (myj == 0 && found < 0) ? s.labelval : myv;
        out_row[myj] = v;
    }
    if (tid == 0)
        out_labels[row] = (float)(found < 0 ? 0 : found);
}

extern "C" void kernel_launch(void* const* d_in, const int* in_sizes, int n_in,
                              void* d_out, int out_size) {
    const float* output = (const float*)d_in[0];
    const int*   labels = (const int*)d_in[1];
    const int batch = in_sizes[1];

    float* out_vals   = (float*)d_out;
    float* out_labels = out_vals + (size_t)batch * RANK;

    logit_selector_kernel<<<batch, NTHREADS>>>(output, labels, out_vals, out_labels);
}

// round 6
// speedup vs baseline: 1.8860x; 1.8860x over previous
#include <cuda_runtime.h>
#include <cstdint>

#define NUM_ITEMS 6714
#define N2 3357            // float2 per row
#define RANK 100
#define NTHREADS 256
#define KPT 14             // float2 per thread
#define THRESH_F 2.0f      // fast-path filter; count(>=2.0) ~ 153 +/- 11 per row here
#define CAND_CAP 1024
#define STOP2 144
#define FINAL_CAP 256
#define MAXWRED 80

__device__ __forceinline__ uint32_t flip_f32(uint32_t s) {
    return s ^ ((s & 0x80000000u) ? 0xFFFFFFFFu : 0x80000000u);
}
__device__ __forceinline__ float unflip_f32(uint32_t k) {
    uint32_t s = (k & 0x80000000u) ? (k ^ 0x80000000u) : ~k;
    return __uint_as_float(s);
}

struct Shared {
    unsigned long long cand[CAND_CAP];  // ((u64)(~key)<<32)|idx : ascending == (key desc, idx asc)
    unsigned long long fin[FINAL_CAP];
    uint32_t wred[MAXWRED][8];
    uint32_t cnt0, cntF;
    int found;
    float labelval;
};

__global__ __launch_bounds__(NTHREADS) void logit_selector_kernel(
    const float* __restrict__ output,
    const int* __restrict__ labels,
    float* __restrict__ out_vals,
    float* __restrict__ out_labels)
{
    __shared__ Shared s;

    const int row  = blockIdx.x;
    const int tid  = threadIdx.x;
    const int lane = tid & 31;
    const int wid  = tid >> 5;
    const float* row_ptr = output + (size_t)row * NUM_ITEMS;
    const float2* row2 = reinterpret_cast<const float2*>(row_ptr);
    const int label = labels[row];

    // ---- front-batched load: all 14 float2 in flight before any dependency ----
    float2 v[KPT];
    #pragma unroll
    for (int j = 0; j < KPT; ++j) {
        int i2 = tid + j * NTHREADS;
        if (i2 < N2) v[j] = row2[i2];
        else { v[j].x = -1e30f; v[j].y = -1e30f; }
    }
    if (tid == 0) {
        s.cnt0 = 0u; s.cntF = 0u; s.found = -1;
        s.labelval = row_ptr[label];
    }
    __syncthreads();

    // ---- filter + warp-aggregated compact from registers (fixed 14 iterations) ----
    #pragma unroll
    for (int j = 0; j < KPT; ++j) {
        int i2 = tid + j * NTHREADS;
        bool pa = v[j].x >= THRESH_F;
        bool pb = v[j].y >= THRESH_F;
        uint32_t ma = __ballot_sync(0xFFFFFFFFu, pa);
        uint32_t mb = __ballot_sync(0xFFFFFFFFu, pb);
        if (ma | mb) {
            uint32_t tot = (uint32_t)(__popc(ma) + __popc(mb));
            uint32_t base = 0;
            if (lane == 0) base = atomicAdd(&s.cnt0, tot);
            base = __shfl_sync(0xFFFFFFFFu, base, 0);
            uint32_t lmask = (1u << lane) - 1u;
            if (pa) {
                uint32_t key = flip_f32(__float_as_uint(v[j].x));
                uint32_t pos = base + (uint32_t)__popc(ma & lmask);
                if (pos < CAND_CAP)
                    s.cand[pos] = ((unsigned long long)(~key) << 32) | (uint32_t)(2 * i2);
            }
            if (pb) {
                uint32_t key = flip_f32(__float_as_uint(v[j].y));
                uint32_t pos = base + (uint32_t)__popc(ma) + (uint32_t)__popc(mb & lmask);
                if (pos < CAND_CAP)
                    s.cand[pos] = ((unsigned long long)(~key) << 32) | (uint32_t)(2 * i2 + 1);
            }
        }
    }
    __syncthreads();

    int iter = 0;

    // ---- fallback: exact bit-narrowing reading global (never runs on this data) ----
    const uint32_t raw0 = s.cnt0;
    if (raw0 < RANK || raw0 > CAND_CAP) {
        __syncthreads();
        if (tid == 0) s.cnt0 = 0u;
        __syncthreads();
        uint32_t pfx = 0u, k = RANK, cand = NUM_ITEMS;
        int sh = 31;
        while (cand > (CAND_CAP - RANK) && sh >= 0 && iter < MAXWRED) {
            const uint32_t t = (pfx << 1) | 1u;
            int c = 0;
            for (int i = tid; i < NUM_ITEMS; i += NTHREADS)
                c += ((flip_f32(__float_as_uint(row_ptr[i])) >> sh) == t);
            c = __reduce_add_sync(0xFFFFFFFFu, c);
            if (lane == 0) s.wred[iter][wid] = (uint32_t)c;
            __syncthreads();
            uint32_t cnt1 = 0;
            #pragma unroll
            for (int w = 0; w < 8; ++w) cnt1 += s.wred[iter][w];
            if (cnt1 >= k) { pfx = t; cand = cnt1; }
            else           { k -= cnt1; pfx <<= 1; cand -= cnt1; }
            --sh; ++iter;
        }
        const uint32_t tf = (sh >= 31) ? 0u : (pfx << (sh + 1));
        for (int i = tid; i < NUM_ITEMS; i += NTHREADS) {
            uint32_t key = flip_f32(__float_as_uint(row_ptr[i]));
            if (key >= tf) {
                uint32_t pos = atomicAdd(&s.cnt0, 1u);   // plain atomics: no collectives
                if (pos < CAND_CAP)
                    s.cand[pos] = ((unsigned long long)(~key) << 32) | (uint32_t)i;
            }
        }
        __syncthreads();
    }
    const uint32_t cnt0 = min(s.cnt0, (uint32_t)CAND_CAP);

    // ---- choose rank source: direct (common) or narrow+gather (cnt0 > 256) ----
    const unsigned long long* fin;
    uint32_t cntN;
    if (cnt0 <= FINAL_CAP) {
        fin = s.cand;                     // rank directly: no narrowing, no gather
        cntN = cnt0;
    } else {
        const uint32_t cnt0_pad = (cnt0 + NTHREADS - 1) / NTHREADS * NTHREADS;
        const uint32_t* ch = reinterpret_cast<const uint32_t*>(s.cand);
        uint32_t pfx = 0u, k = RANK, cand = cnt0;
        int sh = 31;
        while (cand > STOP2 && sh >= 0 && iter < MAXWRED) {
            const uint32_t t = (pfx << 1) | 1u;
            int c = 0;
            for (uint32_t i = tid; i < cnt0; i += NTHREADS)
                c += (((~ch[2 * i + 1]) >> sh) == t);
            c = __reduce_add_sync(0xFFFFFFFFu, c);    // reconverged after loop exit
            if (lane == 0) s.wred[iter][wid] = (uint32_t)c;
            __syncthreads();
            uint32_t cnt1 = 0;
            #pragma unroll
            for (int w = 0; w < 8; ++w) cnt1 += s.wred[iter][w];
            if (cnt1 >= k) { pfx = t; cand = cnt1; }
            else           { k -= cnt1; pfx <<= 1; cand -= cnt1; }
            --sh; ++iter;
        }
        const uint32_t thresh2 = (sh >= 31) ? 0u : (pfx << (sh + 1));

        for (uint32_t i = tid; i < cnt0_pad; i += NTHREADS) {
            unsigned long long p64 = 0ull;
            bool p = false;
            if (i < cnt0) {
                p64 = s.cand[i];
                p = (~(uint32_t)(p64 >> 32)) >= thresh2;
            }
            uint32_t m = __ballot_sync(0xFFFFFFFFu, p);
            if (m) {
                uint32_t base = 0;
                if (lane == 0) base = atomicAdd(&s.cntF, (uint32_t)__popc(m));
                base = __shfl_sync(0xFFFFFFFFu, base, 0);
                if (p) {
                    uint32_t pos = base + (uint32_t)__popc(m & ((1u << lane) - 1u));
                    if (pos < FINAL_CAP) s.fin[pos] = p64;
                }
            }
        }
        __syncthreads();
        fin = s.fin;
        cntN = min(s.cntF, (uint32_t)FINAL_CAP);
    }

    // ---- exact rank via O(n^2) over ~153 candidates (broadcast LDS) ----
    int myj = -1;
    float myv = 0.0f;
    if (tid < (int)cntN) {
        unsigned long long p64 = fin[tid];
        int r = 0;
        for (uint32_t i = 0; i < cntN; ++i)
            r += (fin[i] < p64);
        if (r < RANK) {
            myj = (RANK - 1) - r;
            myv = unflip_f32(~(uint32_t)(p64 >> 32));
            if ((uint32_t)(p64 & 0xFFFFFFFFu) == (uint32_t)label)
                s.found = myj;
        }
    }
    __syncthreads();
    const int found = s.found;

    float* out_row = out_vals + (size_t)row * RANK;
    if (myj >= 0) {
        float vv = (myj == 0 && found < 0) ? s.labelval : myv;
        out_row[myj] = vv;
    }
    if (tid == 0)
        out_labels[row] = (float)(found < 0 ? 0 : found);
}

extern "C" void kernel_launch(void* const* d_in, const int* in_sizes, int n_in,
                              void* d_out, int out_size) {
    const float* output = (const float*)d_in[0];
    const int*   labels = (const int*)d_in[1];
    const int batch = in_sizes[1];

    float* out_vals   = (float*)d_out;
    float* out_labels = out_vals + (size_t)batch * RANK;

    logit_selector_kernel<<<batch, NTHREADS>>>(output, labels, out_vals, out_labels);
}